// round 4
// baseline (speedup 1.0000x reference)
#include <cuda_runtime.h>
#include <math.h>

// ----------------------------------------------------------------------------
// Problem constants
// ----------------------------------------------------------------------------
#define BATCH 8192
#define FDIM  256
#define NBL   8                // blades
#define BF    (BATCH * FDIM)   // 2,097,152

// GEMM tiling
#define BM 128
#define BN 64
#define KT 32

// ----------------------------------------------------------------------------
// Scratch (device globals; no allocation allowed)
// ----------------------------------------------------------------------------
__device__ float g_xt[(size_t)NBL * BF];   // [i][m][b]  (K-major A operand)
__device__ float g_lp[(size_t)NBL * BF];   // left planes  [i][b][n]
__device__ float g_rp[(size_t)NBL * BF];   // right planes [i][b][n]
__device__ float g_wl[4 * FDIM * FDIM];    // [g][m][n]
__device__ float g_wr[4 * FDIM * FDIM];    // [g][m][n]

// ----------------------------------------------------------------------------
// Kernel 1: transpose x [B,F,8] -> planes [i][m][b]
// ----------------------------------------------------------------------------
__global__ void __launch_bounds__(256) k_transpose_x(
    const float* __restrict__ x, float* __restrict__ xt)
{
    int t = blockIdx.x * 256 + threadIdx.x;           // t = m*BATCH + b
    int b = t & (BATCH - 1);
    int m = t >> 13;
    size_t src = ((size_t)b * FDIM + m) * NBL;
    float4 v0 = *(const float4*)&x[src];
    float4 v1 = *(const float4*)&x[src + 4];
    xt[0 * (size_t)BF + t] = v0.x;
    xt[1 * (size_t)BF + t] = v0.y;
    xt[2 * (size_t)BF + t] = v0.z;
    xt[3 * (size_t)BF + t] = v0.w;
    xt[4 * (size_t)BF + t] = v1.x;
    xt[5 * (size_t)BF + t] = v1.y;
    xt[6 * (size_t)BF + t] = v1.z;
    xt[7 * (size_t)BF + t] = v1.w;
}

// ----------------------------------------------------------------------------
// Kernel 2: transpose weights [F_out, F_in, 4] -> [g][m(F_in)][n(F_out)]
// ----------------------------------------------------------------------------
__global__ void __launch_bounds__(256) k_transpose_w(
    const float* __restrict__ wl, const float* __restrict__ wr,
    float* __restrict__ wlt, float* __restrict__ wrt)
{
    int t = blockIdx.x * 256 + threadIdx.x;           // t = m*F + n
    int n = t & (FDIM - 1);
    int m = t >> 8;
    size_t src = ((size_t)n * FDIM + m) * 4;
    float4 a = *(const float4*)&wl[src];
    float4 b = *(const float4*)&wr[src];
    int dst = m * FDIM + n;
    wlt[0 * FDIM * FDIM + dst] = a.x;
    wlt[1 * FDIM * FDIM + dst] = a.y;
    wlt[2 * FDIM * FDIM + dst] = a.z;
    wlt[3 * FDIM * FDIM + dst] = a.w;
    wrt[0 * FDIM * FDIM + dst] = b.x;
    wrt[1 * FDIM * FDIM + dst] = b.y;
    wrt[2 * FDIM * FDIM + dst] = b.z;
    wrt[3 * FDIM * FDIM + dst] = b.w;
}

// ----------------------------------------------------------------------------
// Kernel 3: dual GEMM per blade.
//   lp[i][b][n] = sum_m xt[i][m][b] * wlt[g(i)][m][n]
//   rp[i][b][n] = sum_m xt[i][m][b] * wrt[g(i)][m][n]
// grid (BATCH/BM, FDIM/BN, 8), block 256, thread tile 8x4, dual output.
// ----------------------------------------------------------------------------
__global__ void __launch_bounds__(256) k_gemm_dual(
    const float* __restrict__ xt,
    const float* __restrict__ wlt, const float* __restrict__ wrt,
    float* __restrict__ lp, float* __restrict__ rp)
{
    __shared__ float As[KT][BM];
    __shared__ float Ls[KT][BN];
    __shared__ float Rs[KT][BN];

    const int blade = blockIdx.z;
    const int g = (blade == 0) ? 0 : (blade < 4) ? 1 : (blade < 7) ? 2 : 3;
    const int b0 = blockIdx.x * BM;
    const int n0 = blockIdx.y * BN;

    const float* Ag = xt + (size_t)blade * BF + b0;       // + k*BATCH + b
    const float* Lg = wlt + (size_t)g * FDIM * FDIM + n0; // + k*FDIM + n
    const float* Rg = wrt + (size_t)g * FDIM * FDIM + n0;

    const int tid = threadIdx.x;
    const int r = tid & 15;   // row group (8 rows each)
    const int c = tid >> 4;   // col group (4 cols each)

    float accL[8][4];
    float accR[8][4];
#pragma unroll
    for (int u = 0; u < 8; u++)
#pragma unroll
        for (int v = 0; v < 4; v++) { accL[u][v] = 0.f; accR[u][v] = 0.f; }

    for (int kt = 0; kt < FDIM; kt += KT) {
        // A tile: KT x BM = 4096 floats = 1024 float4 -> 4 per thread
#pragma unroll
        for (int it = 0; it < 4; it++) {
            int idx = it * 256 + tid;
            int kk = idx >> 5;        // BM/4 = 32 float4 per k-row
            int bq = idx & 31;
            *(float4*)&As[kk][bq * 4] =
                *(const float4*)&Ag[(size_t)(kt + kk) * BATCH + bq * 4];
        }
        // W tiles: KT x BN = 2048 floats = 512 float4 -> 2 per thread each
#pragma unroll
        for (int it = 0; it < 2; it++) {
            int idx = it * 256 + tid;
            int kk = idx >> 4;        // BN/4 = 16 float4 per k-row
            int nq = idx & 15;
            *(float4*)&Ls[kk][nq * 4] =
                *(const float4*)&Lg[(kt + kk) * FDIM + nq * 4];
            *(float4*)&Rs[kk][nq * 4] =
                *(const float4*)&Rg[(kt + kk) * FDIM + nq * 4];
        }
        __syncthreads();

#pragma unroll
        for (int k = 0; k < KT; k++) {
            float4 a0 = *(float4*)&As[k][r * 8];
            float4 a1 = *(float4*)&As[k][r * 8 + 4];
            float4 bl = *(float4*)&Ls[k][c * 4];
            float4 br = *(float4*)&Rs[k][c * 4];
            float av[8] = {a0.x, a0.y, a0.z, a0.w, a1.x, a1.y, a1.z, a1.w};
            float blv[4] = {bl.x, bl.y, bl.z, bl.w};
            float brv[4] = {br.x, br.y, br.z, br.w};
#pragma unroll
            for (int u = 0; u < 8; u++) {
#pragma unroll
                for (int v = 0; v < 4; v++) {
                    accL[u][v] += av[u] * blv[v];
                    accR[u][v] += av[u] * brv[v];
                }
            }
        }
        __syncthreads();
    }

    // write planes [i][b][n]
    size_t base = (size_t)blade * BF;
#pragma unroll
    for (int u = 0; u < 8; u++) {
        int bb = b0 + r * 8 + u;
        size_t o = base + (size_t)bb * FDIM + n0 + c * 4;
        float4 vl = make_float4(accL[u][0], accL[u][1], accL[u][2], accL[u][3]);
        float4 vr = make_float4(accR[u][0], accR[u][1], accR[u][2], accR[u][3]);
        *(float4*)&lp[o] = vl;
        *(float4*)&rp[o] = vr;
    }
}

// ----------------------------------------------------------------------------
// Kernel 4: pointwise — normalize xr per grade, sparse Cayley geometric
// product, bias on scalar blade, 1/sqrt(2) scale.
// Tables live as function-local const arrays; with the fully unrolled 8x8
// loop every index/sign/path is folded to an immediate by ptxas.
// ----------------------------------------------------------------------------
__global__ void __launch_bounds__(256) k_pointwise(
    const float* __restrict__ x,
    const float* __restrict__ lp, const float* __restrict__ rp,
    const float* __restrict__ b_left, const float* __restrict__ a_norm,
    const float* __restrict__ w_gp, float* __restrict__ out)
{
    // blade order (grade, lex): 1, e1, e2, e3, e12, e13, e23, e123
    const int MASKv[8] = {0, 1, 2, 4, 3, 5, 6, 7};   // blade index -> bitmask
    const int IDXv[8]  = {0, 1, 2, 4, 3, 5, 6, 7};   // bitmask -> blade index
    const int GRDv[8]  = {0, 1, 1, 1, 2, 2, 2, 3};   // blade index -> grade
    // path index for (grade_i, grade_j, grade_k), lexicographic over the
    // 20 nonzero grade-paths of Cl(3,0)
    const signed char PIDXv[4][4][4] = {
        { { 0,-1,-1,-1}, {-1, 1,-1,-1}, {-1,-1, 2,-1}, {-1,-1,-1, 3} },
        { {-1, 4,-1,-1}, { 5,-1, 6,-1}, {-1, 7,-1, 8}, {-1,-1, 9,-1} },
        { {-1,-1,10,-1}, {-1,11,-1,12}, {13,-1,14,-1}, {-1,15,-1,-1} },
        { {-1,-1,-1,16}, {-1,-1,17,-1}, {-1,18,-1,-1}, {19,-1,-1,-1} },
    };

    int t = blockIdx.x * 256 + threadIdx.x;   // t = b*FDIM + n
    int n = t & (FDIM - 1);

    float xr[8], lf[8], xv[8];
#pragma unroll
    for (int i = 0; i < 8; i++) {
        xr[i] = rp[(size_t)i * BF + t];
        lf[i] = lp[(size_t)i * BF + t];
    }
    {
        float4 v0 = *(const float4*)&x[(size_t)t * 8];
        float4 v1 = *(const float4*)&x[(size_t)t * 8 + 4];
        xv[0] = v0.x; xv[1] = v0.y; xv[2] = v0.z; xv[3] = v0.w;
        xv[4] = v1.x; xv[5] = v1.y; xv[6] = v1.z; xv[7] = v1.w;
    }

    // per-grade quadratic forms (Euclidean: plain sum of squares)
    float qs[4];
    qs[0] = xr[0] * xr[0];
    qs[1] = xr[1] * xr[1] + xr[2] * xr[2] + xr[3] * xr[3];
    qs[2] = xr[4] * xr[4] + xr[5] * xr[5] + xr[6] * xr[6];
    qs[3] = xr[7] * xr[7];

    float invn[4];
#pragma unroll
    for (int gg = 0; gg < 4; gg++) {
        float nrm = sqrtf(sqrtf(qs[gg] * qs[gg] + 1e-16f));   // (q^2+1e-16)^0.25
        float a = a_norm[n * 4 + gg];
        float sig = 1.0f / (1.0f + expf(-a));
        float d = sig * (nrm - 1.0f) + 1.0f + 1e-6f;
        invn[gg] = 1.0f / d;
    }

    float xrn[8];
    xrn[0] = xr[0] * invn[0];
    xrn[1] = xr[1] * invn[1];
    xrn[2] = xr[2] * invn[1];
    xrn[3] = xr[3] * invn[1];
    xrn[4] = xr[4] * invn[2];
    xrn[5] = xr[5] * invn[2];
    xrn[6] = xr[6] * invn[2];
    xrn[7] = xr[7] * invn[3];

    // path weights for this feature
    float wp[20];
#pragma unroll
    for (int p = 0; p < 20; p++) wp[p] = __ldg(&w_gp[n * 20 + p]);

    float gp[8];
#pragma unroll
    for (int j = 0; j < 8; j++) gp[j] = 0.f;

#pragma unroll
    for (int i = 0; i < 8; i++) {
#pragma unroll
        for (int k = 0; k < 8; k++) {
            const int mi = MASKv[i];
            const int mk = MASKv[k];
            const int j = IDXv[mi ^ mk];
            // reordering sign: popcount((mi>>1)&mk) + popcount((mi>>2)&mk)
            const int s1 = ((mi >> 1) & mk);
            const int s2 = ((mi >> 2) & mk);
            const int sgn = ((s1 & 1) + ((s1 >> 1) & 1) + ((s1 >> 2) & 1)
                           + (s2 & 1) + ((s2 >> 1) & 1) + ((s2 >> 2) & 1)) & 1;
            const int p = PIDXv[GRDv[i]][GRDv[j]][GRDv[k]];
            float term = xv[i] * xrn[k];
            float w = wp[p];
            gp[j] += sgn ? (-w * term) : (w * term);
        }
    }

    lf[0] += b_left[n];

    const float rs2 = 0.70710678118654752440f;
    float4 o0 = make_float4((lf[0] + gp[0]) * rs2, (lf[1] + gp[1]) * rs2,
                            (lf[2] + gp[2]) * rs2, (lf[3] + gp[3]) * rs2);
    float4 o1 = make_float4((lf[4] + gp[4]) * rs2, (lf[5] + gp[5]) * rs2,
                            (lf[6] + gp[6]) * rs2, (lf[7] + gp[7]) * rs2);
    *(float4*)&out[(size_t)t * 8] = o0;
    *(float4*)&out[(size_t)t * 8 + 4] = o1;
}

// ----------------------------------------------------------------------------
// Launch — inputs (metadata order): x, w_left, b_left, w_right, a_norm, w_gp
// ----------------------------------------------------------------------------
extern "C" void kernel_launch(void* const* d_in, const int* in_sizes, int n_in,
                              void* d_out, int out_size)
{
    const float* x       = (const float*)d_in[0];
    const float* w_left  = (const float*)d_in[1];
    const float* b_left  = (const float*)d_in[2];
    const float* w_right = (const float*)d_in[3];
    const float* a_norm  = (const float*)d_in[4];
    const float* w_gp    = (const float*)d_in[5];
    float* out = (float*)d_out;

    float *xt, *lp, *rp, *wlt, *wrt;
    cudaGetSymbolAddress((void**)&xt,  g_xt);
    cudaGetSymbolAddress((void**)&lp,  g_lp);
    cudaGetSymbolAddress((void**)&rp,  g_rp);
    cudaGetSymbolAddress((void**)&wlt, g_wl);
    cudaGetSymbolAddress((void**)&wrt, g_wr);

    k_transpose_x<<<BF / 256, 256>>>(x, xt);
    k_transpose_w<<<(FDIM * FDIM) / 256, 256>>>(w_left, w_right, wlt, wrt);

    dim3 gg(BATCH / BM, FDIM / BN, NBL);
    k_gemm_dual<<<gg, 256>>>(xt, wlt, wrt, lp, rp);

    k_pointwise<<<BF / 256, 256>>>(x, lp, rp, b_left, a_norm, w_gp, out);
}

// round 7
// speedup vs baseline: 2.1823x; 2.1823x over previous
#include <cuda_runtime.h>
#include <cstdint>
#include <math.h>

// ----------------------------------------------------------------------------
// Problem constants
// ----------------------------------------------------------------------------
#define BATCH 8192
#define FDIM  256
#define NBL   8
#define BF    (BATCH * FDIM)   // 2,097,152

// GEMM tiling (mma.sync m16n8k8 tf32)
#define TM 128          // batch rows per CTA
#define TN 64           // output features per CTA (dual: L and R)
#define KT 32           // K chunk per stage
#define SPAD 36         // padded smem row stride (floats) -> conflict-free

// ----------------------------------------------------------------------------
// Scratch (device globals; no allocation allowed)
// ----------------------------------------------------------------------------
__device__ float g_xt[(size_t)NBL * BF];   // planes [i][b][k], tf32-rounded
__device__ float g_lp[(size_t)NBL * BF];   // left planes  [i][b][n]
__device__ float g_rp[(size_t)NBL * BF];   // right planes [i][b][n]
__device__ float g_wl[4 * FDIM * FDIM];    // [g][n][k] (col-major KxN), tf32-rounded
__device__ float g_wr[4 * FDIM * FDIM];    // [g][n][k], tf32-rounded

// ----------------------------------------------------------------------------
// tf32 helpers (base-ISA only; no tcgen05 on this compile target)
// ----------------------------------------------------------------------------
__device__ __forceinline__ float to_tf32(float x) {
    float y;
    asm("cvt.rna.tf32.f32 %0, %1;" : "=f"(y) : "f"(x));
    return y;
}

#define MMA_TF32(d, a, b0r, b1r) \
    asm volatile( \
        "mma.sync.aligned.m16n8k8.row.col.f32.tf32.tf32.f32 " \
        "{%0,%1,%2,%3}, {%4,%5,%6,%7}, {%8,%9}, {%0,%1,%2,%3};" \
        : "+f"((d)[0]), "+f"((d)[1]), "+f"((d)[2]), "+f"((d)[3]) \
        : "r"((a)[0]), "r"((a)[1]), "r"((a)[2]), "r"((a)[3]), \
          "r"(b0r), "r"(b1r))

// ----------------------------------------------------------------------------
// Kernel 1: transpose x [B,F,8] -> planes [i][b][k], rounding to tf32.
// t = b*256 + m. Reads: lane-consecutive 32B chunks (coalesced).
// Writes: plane[i][t] lane-consecutive (coalesced).
// ----------------------------------------------------------------------------
__global__ void __launch_bounds__(256) k_transpose_x(
    const float* __restrict__ x, float* __restrict__ xt)
{
    int t = blockIdx.x * 256 + threadIdx.x;   // t = b*FDIM + m
    size_t src = (size_t)t * NBL;
    float4 v0 = *(const float4*)&x[src];
    float4 v1 = *(const float4*)&x[src + 4];
    xt[0 * (size_t)BF + t] = to_tf32(v0.x);
    xt[1 * (size_t)BF + t] = to_tf32(v0.y);
    xt[2 * (size_t)BF + t] = to_tf32(v0.z);
    xt[3 * (size_t)BF + t] = to_tf32(v0.w);
    xt[4 * (size_t)BF + t] = to_tf32(v1.x);
    xt[5 * (size_t)BF + t] = to_tf32(v1.y);
    xt[6 * (size_t)BF + t] = to_tf32(v1.z);
    xt[7 * (size_t)BF + t] = to_tf32(v1.w);
}

// ----------------------------------------------------------------------------
// Kernel 2: de-interleave weights [n, k, 4] -> [g][n][k], rounding to tf32.
// ----------------------------------------------------------------------------
__global__ void __launch_bounds__(256) k_prep_w(
    const float* __restrict__ wl, const float* __restrict__ wr,
    float* __restrict__ wlt, float* __restrict__ wrt)
{
    int t = blockIdx.x * 256 + threadIdx.x;   // t = n*FDIM + k
    size_t src = (size_t)t * 4;
    float4 a = *(const float4*)&wl[src];
    float4 b = *(const float4*)&wr[src];
    wlt[0 * FDIM * FDIM + t] = to_tf32(a.x);
    wlt[1 * FDIM * FDIM + t] = to_tf32(a.y);
    wlt[2 * FDIM * FDIM + t] = to_tf32(a.z);
    wlt[3 * FDIM * FDIM + t] = to_tf32(a.w);
    wrt[0 * FDIM * FDIM + t] = to_tf32(b.x);
    wrt[1 * FDIM * FDIM + t] = to_tf32(b.y);
    wrt[2 * FDIM * FDIM + t] = to_tf32(b.z);
    wrt[3 * FDIM * FDIM + t] = to_tf32(b.w);
}

// ----------------------------------------------------------------------------
// Kernel 3: tf32 mma.sync dual GEMM.
//   lp[i][b][n] = sum_k xt[i][b][k] * wlt[g(i)][n][k]   (and rp with wrt)
// grid (BATCH/TM, FDIM/TN, NBL), 256 threads (8 warps, 4x2).
// Warp tile 32x32 per output. Smem pad 36 -> all LDS/STS conflict-free.
// ----------------------------------------------------------------------------
__global__ void __launch_bounds__(256, 2) k_gemm_mma(
    const float* __restrict__ xt,
    const float* __restrict__ wlt, const float* __restrict__ wrt,
    float* __restrict__ lp, float* __restrict__ rp)
{
    __shared__ float As [TM * SPAD];   // [m][k] row-major, padded
    __shared__ float BLs[TN * SPAD];   // [n][k] (col-major KxN), padded
    __shared__ float BRs[TN * SPAD];

    const int tid  = threadIdx.x;
    const int lane = tid & 31;
    const int w    = tid >> 5;
    const int gq   = lane >> 2;   // group id (0..7)
    const int tq   = lane & 3;    // thread-in-group (0..3)

    const int blade = blockIdx.z;
    const int grd = (blade == 0) ? 0 : (blade < 4) ? 1 : (blade < 7) ? 2 : 3;
    const int b0  = blockIdx.x * TM;
    const int n0c = blockIdx.y * TN;

    const float* Ap  = xt  + (size_t)blade * BF + (size_t)b0 * FDIM;
    const float* WLp = wlt + (size_t)grd * FDIM * FDIM + (size_t)n0c * FDIM;
    const float* WRp = wrt + (size_t)grd * FDIM * FDIM + (size_t)n0c * FDIM;

    const int mw = w >> 1;        // 0..3
    const int nw = w & 1;         // 0..1
    const int m0 = mw * 32;
    const int n0w = nw * 32;

    float acc[2][2][4][4];        // [out L/R][mi][ni][reg]
#pragma unroll
    for (int o = 0; o < 2; o++)
#pragma unroll
        for (int mi = 0; mi < 2; mi++)
#pragma unroll
            for (int ni = 0; ni < 4; ni++)
#pragma unroll
                for (int q = 0; q < 4; q++) acc[o][mi][ni][q] = 0.f;

    for (int c = 0; c < FDIM / KT; c++) {
        const int kt = c * KT;
        // A tile: 128 rows x 32 k -> 1024 float4, 4 per thread
#pragma unroll
        for (int it = 0; it < 4; it++) {
            int id = it * 256 + tid;
            int m = id >> 3, q = id & 7;
            *(float4*)&As[m * SPAD + q * 4] =
                *(const float4*)&Ap[(size_t)m * FDIM + kt + q * 4];
        }
        // B tiles: 64 rows x 32 k each -> 512 float4, 2 per thread each
#pragma unroll
        for (int it = 0; it < 2; it++) {
            int id = it * 256 + tid;
            int n = id >> 3, q = id & 7;
            *(float4*)&BLs[n * SPAD + q * 4] =
                *(const float4*)&WLp[(size_t)n * FDIM + kt + q * 4];
            *(float4*)&BRs[n * SPAD + q * 4] =
                *(const float4*)&WRp[(size_t)n * FDIM + kt + q * 4];
        }
        __syncthreads();

#pragma unroll
        for (int ks = 0; ks < KT / 8; ks++) {
            const int kk = ks * 8;
            uint32_t a[2][4];
#pragma unroll
            for (int mi = 0; mi < 2; mi++) {
                const float* ab = &As[(m0 + mi * 16 + gq) * SPAD + kk];
                a[mi][0] = __float_as_uint(ab[tq]);
                a[mi][1] = __float_as_uint(ab[8 * SPAD + tq]);
                a[mi][2] = __float_as_uint(ab[tq + 4]);
                a[mi][3] = __float_as_uint(ab[8 * SPAD + tq + 4]);
            }
#pragma unroll
            for (int ni = 0; ni < 4; ni++) {
                const float* bl = &BLs[(n0w + ni * 8 + gq) * SPAD + kk];
                uint32_t bl0 = __float_as_uint(bl[tq]);
                uint32_t bl1 = __float_as_uint(bl[tq + 4]);
                const float* br = &BRs[(n0w + ni * 8 + gq) * SPAD + kk];
                uint32_t br0 = __float_as_uint(br[tq]);
                uint32_t br1 = __float_as_uint(br[tq + 4]);
#pragma unroll
                for (int mi = 0; mi < 2; mi++) {
                    MMA_TF32(acc[0][mi][ni], a[mi], bl0, bl1);
                    MMA_TF32(acc[1][mi][ni], a[mi], br0, br1);
                }
            }
        }
        __syncthreads();
    }

    // epilogue: D frag mapping c0:(g,2t) c1:(g,2t+1) c2:(g+8,2t) c3:(g+8,2t+1)
#pragma unroll
    for (int o = 0; o < 2; o++) {
        float* base = (o ? rp : lp) + (size_t)blade * BF;
#pragma unroll
        for (int mi = 0; mi < 2; mi++) {
            int row = b0 + m0 + mi * 16 + gq;
#pragma unroll
            for (int ni = 0; ni < 4; ni++) {
                int col = n0c + n0w + ni * 8 + tq * 2;
                *(float2*)&base[(size_t)row * FDIM + col] =
                    make_float2(acc[o][mi][ni][0], acc[o][mi][ni][1]);
                *(float2*)&base[(size_t)(row + 8) * FDIM + col] =
                    make_float2(acc[o][mi][ni][2], acc[o][mi][ni][3]);
            }
        }
    }
}

// ----------------------------------------------------------------------------
// Kernel 4: pointwise (unchanged from passing R4 version)
// ----------------------------------------------------------------------------
__global__ void __launch_bounds__(256) k_pointwise(
    const float* __restrict__ x,
    const float* __restrict__ lp, const float* __restrict__ rp,
    const float* __restrict__ b_left, const float* __restrict__ a_norm,
    const float* __restrict__ w_gp, float* __restrict__ out)
{
    const int MASKv[8] = {0, 1, 2, 4, 3, 5, 6, 7};
    const int IDXv[8]  = {0, 1, 2, 4, 3, 5, 6, 7};
    const int GRDv[8]  = {0, 1, 1, 1, 2, 2, 2, 3};
    const signed char PIDXv[4][4][4] = {
        { { 0,-1,-1,-1}, {-1, 1,-1,-1}, {-1,-1, 2,-1}, {-1,-1,-1, 3} },
        { {-1, 4,-1,-1}, { 5,-1, 6,-1}, {-1, 7,-1, 8}, {-1,-1, 9,-1} },
        { {-1,-1,10,-1}, {-1,11,-1,12}, {13,-1,14,-1}, {-1,15,-1,-1} },
        { {-1,-1,-1,16}, {-1,-1,17,-1}, {-1,18,-1,-1}, {19,-1,-1,-1} },
    };

    int t = blockIdx.x * 256 + threadIdx.x;   // t = b*FDIM + n
    int n = t & (FDIM - 1);

    float xr[8], lf[8], xv[8];
#pragma unroll
    for (int i = 0; i < 8; i++) {
        xr[i] = rp[(size_t)i * BF + t];
        lf[i] = lp[(size_t)i * BF + t];
    }
    {
        float4 v0 = *(const float4*)&x[(size_t)t * 8];
        float4 v1 = *(const float4*)&x[(size_t)t * 8 + 4];
        xv[0] = v0.x; xv[1] = v0.y; xv[2] = v0.z; xv[3] = v0.w;
        xv[4] = v1.x; xv[5] = v1.y; xv[6] = v1.z; xv[7] = v1.w;
    }

    float qs[4];
    qs[0] = xr[0] * xr[0];
    qs[1] = xr[1] * xr[1] + xr[2] * xr[2] + xr[3] * xr[3];
    qs[2] = xr[4] * xr[4] + xr[5] * xr[5] + xr[6] * xr[6];
    qs[3] = xr[7] * xr[7];

    float invn[4];
#pragma unroll
    for (int gg = 0; gg < 4; gg++) {
        float nrm = sqrtf(sqrtf(qs[gg] * qs[gg] + 1e-16f));
        float a = a_norm[n * 4 + gg];
        float sig = 1.0f / (1.0f + expf(-a));
        float d = sig * (nrm - 1.0f) + 1.0f + 1e-6f;
        invn[gg] = 1.0f / d;
    }

    float xrn[8];
    xrn[0] = xr[0] * invn[0];
    xrn[1] = xr[1] * invn[1];
    xrn[2] = xr[2] * invn[1];
    xrn[3] = xr[3] * invn[1];
    xrn[4] = xr[4] * invn[2];
    xrn[5] = xr[5] * invn[2];
    xrn[6] = xr[6] * invn[2];
    xrn[7] = xr[7] * invn[3];

    float wp[20];
#pragma unroll
    for (int p = 0; p < 20; p++) wp[p] = __ldg(&w_gp[n * 20 + p]);

    float gp[8];
#pragma unroll
    for (int j = 0; j < 8; j++) gp[j] = 0.f;

#pragma unroll
    for (int i = 0; i < 8; i++) {
#pragma unroll
        for (int k = 0; k < 8; k++) {
            const int mi = MASKv[i];
            const int mk = MASKv[k];
            const int j = IDXv[mi ^ mk];
            const int s1 = ((mi >> 1) & mk);
            const int s2 = ((mi >> 2) & mk);
            const int sgn = ((s1 & 1) + ((s1 >> 1) & 1) + ((s1 >> 2) & 1)
                           + (s2 & 1) + ((s2 >> 1) & 1) + ((s2 >> 2) & 1)) & 1;
            const int p = PIDXv[GRDv[i]][GRDv[j]][GRDv[k]];
            float term = xv[i] * xrn[k];
            float ww = wp[p];
            gp[j] += sgn ? (-ww * term) : (ww * term);
        }
    }

    lf[0] += b_left[n];

    const float rs2 = 0.70710678118654752440f;
    float4 o0 = make_float4((lf[0] + gp[0]) * rs2, (lf[1] + gp[1]) * rs2,
                            (lf[2] + gp[2]) * rs2, (lf[3] + gp[3]) * rs2);
    float4 o1 = make_float4((lf[4] + gp[4]) * rs2, (lf[5] + gp[5]) * rs2,
                            (lf[6] + gp[6]) * rs2, (lf[7] + gp[7]) * rs2);
    *(float4*)&out[(size_t)t * 8] = o0;
    *(float4*)&out[(size_t)t * 8 + 4] = o1;
}

// ----------------------------------------------------------------------------
// Launch — inputs (metadata order): x, w_left, b_left, w_right, a_norm, w_gp
// ----------------------------------------------------------------------------
extern "C" void kernel_launch(void* const* d_in, const int* in_sizes, int n_in,
                              void* d_out, int out_size)
{
    const float* x       = (const float*)d_in[0];
    const float* w_left  = (const float*)d_in[1];
    const float* b_left  = (const float*)d_in[2];
    const float* w_right = (const float*)d_in[3];
    const float* a_norm  = (const float*)d_in[4];
    const float* w_gp    = (const float*)d_in[5];
    float* out = (float*)d_out;

    float *xt, *lp, *rp, *wlt, *wrt;
    cudaGetSymbolAddress((void**)&xt,  g_xt);
    cudaGetSymbolAddress((void**)&lp,  g_lp);
    cudaGetSymbolAddress((void**)&rp,  g_rp);
    cudaGetSymbolAddress((void**)&wlt, g_wl);
    cudaGetSymbolAddress((void**)&wrt, g_wr);

    k_transpose_x<<<BF / 256, 256>>>(x, xt);
    k_prep_w<<<(FDIM * FDIM) / 256, 256>>>(w_left, w_right, wlt, wrt);

    dim3 gg(BATCH / TM, FDIM / TN, NBL);
    k_gemm_mma<<<gg, 256>>>(xt, wlt, wrt, lp, rp);

    k_pointwise<<<BF / 256, 256>>>(x, lp, rp, b_left, a_norm, w_gp, out);
}

// round 8
// speedup vs baseline: 2.9541x; 1.3537x over previous
#include <cuda_runtime.h>
#include <cuda_fp16.h>
#include <cstdint>
#include <math.h>

// ----------------------------------------------------------------------------
// Problem constants
// ----------------------------------------------------------------------------
#define BATCH 8192
#define FDIM  256
#define NBL   8
#define BF    (BATCH * FDIM)   // 2,097,152

// GEMM tiling (mma.sync m16n8k16 fp16)
#define TM 128          // batch rows per CTA
#define TN 64           // output features per CTA (dual outputs L and R)
#define KT 32           // K chunk per stage
#define SPADH 40        // padded smem row stride in halves -> conflict-free frags

// ----------------------------------------------------------------------------
// Scratch (device globals; no allocation allowed)
// ----------------------------------------------------------------------------
__device__ __half g_xt[(size_t)NBL * BF];   // planes [i][b][k], fp16
__device__ float  g_lp[(size_t)NBL * BF];   // left planes  [i][b][n]
__device__ float  g_rp[(size_t)NBL * BF];   // right planes [i][b][n]
__device__ __half g_wl[4 * FDIM * FDIM];    // [g][n][k] fp16
__device__ __half g_wr[4 * FDIM * FDIM];    // [g][n][k] fp16

// ----------------------------------------------------------------------------
// helpers (base-ISA only: mma.sync + cp.async; no tcgen05 on this target)
// ----------------------------------------------------------------------------
__device__ __forceinline__ uint32_t smem_u32(const void* p) {
    uint32_t a;
    asm("{ .reg .u64 t; cvta.to.shared.u64 t, %1; cvt.u32.u64 %0, t; }"
        : "=r"(a) : "l"(p));
    return a;
}

__device__ __forceinline__ void cp16(uint32_t s, const void* g) {
    asm volatile("cp.async.cg.shared.global [%0], [%1], 16;" :: "r"(s), "l"(g));
}

#define CP_COMMIT() asm volatile("cp.async.commit_group;" ::: "memory")
#define CP_WAIT(n)  asm volatile("cp.async.wait_group %0;" :: "n"(n) : "memory")

#define MMA_FP16(d, a, b0r, b1r) \
    asm volatile( \
        "mma.sync.aligned.m16n8k16.row.col.f32.f16.f16.f32 " \
        "{%0,%1,%2,%3}, {%4,%5,%6,%7}, {%8,%9}, {%0,%1,%2,%3};" \
        : "+f"((d)[0]), "+f"((d)[1]), "+f"((d)[2]), "+f"((d)[3]) \
        : "r"((a)[0]), "r"((a)[1]), "r"((a)[2]), "r"((a)[3]), \
          "r"(b0r), "r"(b1r))

// ----------------------------------------------------------------------------
// Kernel 1: transpose x [B,F,8] -> fp16 planes [i][b][k]
// ----------------------------------------------------------------------------
__global__ void __launch_bounds__(256) k_transpose_x(
    const float* __restrict__ x, __half* __restrict__ xt)
{
    int t = blockIdx.x * 256 + threadIdx.x;   // t = b*FDIM + k
    size_t src = (size_t)t * NBL;
    float4 v0 = *(const float4*)&x[src];
    float4 v1 = *(const float4*)&x[src + 4];
    xt[0 * (size_t)BF + t] = __float2half_rn(v0.x);
    xt[1 * (size_t)BF + t] = __float2half_rn(v0.y);
    xt[2 * (size_t)BF + t] = __float2half_rn(v0.z);
    xt[3 * (size_t)BF + t] = __float2half_rn(v0.w);
    xt[4 * (size_t)BF + t] = __float2half_rn(v1.x);
    xt[5 * (size_t)BF + t] = __float2half_rn(v1.y);
    xt[6 * (size_t)BF + t] = __float2half_rn(v1.z);
    xt[7 * (size_t)BF + t] = __float2half_rn(v1.w);
}

// ----------------------------------------------------------------------------
// Kernel 2: de-interleave weights [n, k, 4] -> fp16 [g][n][k]
// ----------------------------------------------------------------------------
__global__ void __launch_bounds__(256) k_prep_w(
    const float* __restrict__ wl, const float* __restrict__ wr,
    __half* __restrict__ wlt, __half* __restrict__ wrt)
{
    int t = blockIdx.x * 256 + threadIdx.x;   // t = n*FDIM + k
    size_t src = (size_t)t * 4;
    float4 a = *(const float4*)&wl[src];
    float4 b = *(const float4*)&wr[src];
    wlt[0 * FDIM * FDIM + t] = __float2half_rn(a.x);
    wlt[1 * FDIM * FDIM + t] = __float2half_rn(a.y);
    wlt[2 * FDIM * FDIM + t] = __float2half_rn(a.z);
    wlt[3 * FDIM * FDIM + t] = __float2half_rn(a.w);
    wrt[0 * FDIM * FDIM + t] = __float2half_rn(b.x);
    wrt[1 * FDIM * FDIM + t] = __float2half_rn(b.y);
    wrt[2 * FDIM * FDIM + t] = __float2half_rn(b.z);
    wrt[3 * FDIM * FDIM + t] = __float2half_rn(b.w);
}

// ----------------------------------------------------------------------------
// Kernel 3: fp16 mma.sync dual GEMM with 2-stage cp.async pipeline.
//   lp[i][b][n] = sum_k xt[i][b][k] * wlt[g(i)][n][k]   (and rp with wrt)
// grid (BATCH/TM, FDIM/TN, NBL), 256 threads (8 warps, 4x2), warp tile 32x32x2.
// ----------------------------------------------------------------------------
__global__ void __launch_bounds__(256, 2) k_gemm_mma(
    const __half* __restrict__ xt,
    const __half* __restrict__ wlt, const __half* __restrict__ wrt,
    float* __restrict__ lp, float* __restrict__ rp)
{
    __shared__ __half As [2][TM * SPADH];
    __shared__ __half BLs[2][TN * SPADH];
    __shared__ __half BRs[2][TN * SPADH];

    const int tid  = threadIdx.x;
    const int lane = tid & 31;
    const int w    = tid >> 5;
    const int gq   = lane >> 2;   // group (0..7)
    const int tq   = lane & 3;    // thread-in-group (0..3)

    const int blade = blockIdx.z;
    const int grd = (blade == 0) ? 0 : (blade < 4) ? 1 : (blade < 7) ? 2 : 3;
    const int b0  = blockIdx.x * TM;
    const int n0c = blockIdx.y * TN;

    const __half* Ap  = xt  + (size_t)blade * BF + (size_t)b0 * FDIM;
    const __half* WLp = wlt + (size_t)grd * FDIM * FDIM + (size_t)n0c * FDIM;
    const __half* WRp = wrt + (size_t)grd * FDIM * FDIM + (size_t)n0c * FDIM;

    const uint32_t sA  = smem_u32(&As[0][0]);
    const uint32_t sBL = smem_u32(&BLs[0][0]);
    const uint32_t sBR = smem_u32(&BRs[0][0]);
    const uint32_t stageA  = TM * SPADH * 2;   // bytes per stage
    const uint32_t stageB  = TN * SPADH * 2;

    const int mw = w >> 1;        // 0..3
    const int nw = w & 1;         // 0..1
    const int m0 = mw * 32;
    const int n0w = nw * 32;

    // per-thread cp.async assignments
    const int am0 = tid >> 2;            // A rows: tid>>2 and +64
    const int aq  = tid & 3;             // 16B chunk in row (4 per row of 64B)
    const int bn  = tid >> 2;            // B row (0..63)

    float acc[2][2][4][4];
#pragma unroll
    for (int o = 0; o < 2; o++)
#pragma unroll
        for (int mi = 0; mi < 2; mi++)
#pragma unroll
            for (int ni = 0; ni < 4; ni++)
#pragma unroll
                for (int q = 0; q < 4; q++) acc[o][mi][ni][q] = 0.f;

    // ---- pipeline issue helper (macro to keep addresses simple)
#define ISSUE(cc) do { \
    int s_ = (cc) & 1; \
    int kt_ = (cc) * KT; \
    cp16(sA + s_ * stageA + (am0 * SPADH + aq * 8) * 2, \
         Ap + (size_t)am0 * FDIM + kt_ + aq * 8); \
    cp16(sA + s_ * stageA + ((am0 + 64) * SPADH + aq * 8) * 2, \
         Ap + (size_t)(am0 + 64) * FDIM + kt_ + aq * 8); \
    cp16(sBL + s_ * stageB + (bn * SPADH + aq * 8) * 2, \
         WLp + (size_t)bn * FDIM + kt_ + aq * 8); \
    cp16(sBR + s_ * stageB + (bn * SPADH + aq * 8) * 2, \
         WRp + (size_t)bn * FDIM + kt_ + aq * 8); \
} while (0)

    ISSUE(0);
    CP_COMMIT();

    for (int c = 0; c < FDIM / KT; c++) {
        if (c < FDIM / KT - 1) {
            ISSUE(c + 1);
            CP_COMMIT();
            CP_WAIT(1);
        } else {
            CP_WAIT(0);
        }
        __syncthreads();

        const int s = c & 1;
#pragma unroll
        for (int ks = 0; ks < 2; ks++) {
            const int kk = ks * 16 + 2 * tq;
            uint32_t a[2][4];
#pragma unroll
            for (int mi = 0; mi < 2; mi++) {
                const __half* ab = &As[s][(m0 + mi * 16 + gq) * SPADH + kk];
                a[mi][0] = *(const uint32_t*)(ab);
                a[mi][1] = *(const uint32_t*)(ab + 8 * SPADH);
                a[mi][2] = *(const uint32_t*)(ab + 8);
                a[mi][3] = *(const uint32_t*)(ab + 8 * SPADH + 8);
            }
#pragma unroll
            for (int ni = 0; ni < 4; ni++) {
                const __half* blp = &BLs[s][(n0w + ni * 8 + gq) * SPADH + kk];
                uint32_t bl0 = *(const uint32_t*)(blp);
                uint32_t bl1 = *(const uint32_t*)(blp + 8);
                const __half* brp = &BRs[s][(n0w + ni * 8 + gq) * SPADH + kk];
                uint32_t br0 = *(const uint32_t*)(brp);
                uint32_t br1 = *(const uint32_t*)(brp + 8);
#pragma unroll
                for (int mi = 0; mi < 2; mi++) {
                    MMA_FP16(acc[0][mi][ni], a[mi], bl0, bl1);
                    MMA_FP16(acc[1][mi][ni], a[mi], br0, br1);
                }
            }
        }
        __syncthreads();
    }
#undef ISSUE

    // epilogue: D frag c0:(g,2t) c1:(g,2t+1) c2:(g+8,2t) c3:(g+8,2t+1)
#pragma unroll
    for (int o = 0; o < 2; o++) {
        float* base = (o ? rp : lp) + (size_t)blade * BF;
#pragma unroll
        for (int mi = 0; mi < 2; mi++) {
            int row = b0 + m0 + mi * 16 + gq;
#pragma unroll
            for (int ni = 0; ni < 4; ni++) {
                int col = n0c + n0w + ni * 8 + tq * 2;
                *(float2*)&base[(size_t)row * FDIM + col] =
                    make_float2(acc[o][mi][ni][0], acc[o][mi][ni][1]);
                *(float2*)&base[(size_t)(row + 8) * FDIM + col] =
                    make_float2(acc[o][mi][ni][2], acc[o][mi][ni][3]);
            }
        }
    }
}

// ----------------------------------------------------------------------------
// Kernel 4: pointwise (unchanged)
// ----------------------------------------------------------------------------
__global__ void __launch_bounds__(256) k_pointwise(
    const float* __restrict__ x,
    const float* __restrict__ lp, const float* __restrict__ rp,
    const float* __restrict__ b_left, const float* __restrict__ a_norm,
    const float* __restrict__ w_gp, float* __restrict__ out)
{
    const int MASKv[8] = {0, 1, 2, 4, 3, 5, 6, 7};
    const int IDXv[8]  = {0, 1, 2, 4, 3, 5, 6, 7};
    const int GRDv[8]  = {0, 1, 1, 1, 2, 2, 2, 3};
    const signed char PIDXv[4][4][4] = {
        { { 0,-1,-1,-1}, {-1, 1,-1,-1}, {-1,-1, 2,-1}, {-1,-1,-1, 3} },
        { {-1, 4,-1,-1}, { 5,-1, 6,-1}, {-1, 7,-1, 8}, {-1,-1, 9,-1} },
        { {-1,-1,10,-1}, {-1,11,-1,12}, {13,-1,14,-1}, {-1,15,-1,-1} },
        { {-1,-1,-1,16}, {-1,-1,17,-1}, {-1,18,-1,-1}, {19,-1,-1,-1} },
    };

    int t = blockIdx.x * 256 + threadIdx.x;   // t = b*FDIM + n
    int n = t & (FDIM - 1);

    float xr[8], lf[8], xv[8];
#pragma unroll
    for (int i = 0; i < 8; i++) {
        xr[i] = rp[(size_t)i * BF + t];
        lf[i] = lp[(size_t)i * BF + t];
    }
    {
        float4 v0 = *(const float4*)&x[(size_t)t * 8];
        float4 v1 = *(const float4*)&x[(size_t)t * 8 + 4];
        xv[0] = v0.x; xv[1] = v0.y; xv[2] = v0.z; xv[3] = v0.w;
        xv[4] = v1.x; xv[5] = v1.y; xv[6] = v1.z; xv[7] = v1.w;
    }

    float qs[4];
    qs[0] = xr[0] * xr[0];
    qs[1] = xr[1] * xr[1] + xr[2] * xr[2] + xr[3] * xr[3];
    qs[2] = xr[4] * xr[4] + xr[5] * xr[5] + xr[6] * xr[6];
    qs[3] = xr[7] * xr[7];

    float invn[4];
#pragma unroll
    for (int gg = 0; gg < 4; gg++) {
        float nrm = sqrtf(sqrtf(qs[gg] * qs[gg] + 1e-16f));
        float a = a_norm[n * 4 + gg];
        float sig = 1.0f / (1.0f + expf(-a));
        float d = sig * (nrm - 1.0f) + 1.0f + 1e-6f;
        invn[gg] = 1.0f / d;
    }

    float xrn[8];
    xrn[0] = xr[0] * invn[0];
    xrn[1] = xr[1] * invn[1];
    xrn[2] = xr[2] * invn[1];
    xrn[3] = xr[3] * invn[1];
    xrn[4] = xr[4] * invn[2];
    xrn[5] = xr[5] * invn[2];
    xrn[6] = xr[6] * invn[2];
    xrn[7] = xr[7] * invn[3];

    float wp[20];
#pragma unroll
    for (int p = 0; p < 20; p++) wp[p] = __ldg(&w_gp[n * 20 + p]);

    float gp[8];
#pragma unroll
    for (int j = 0; j < 8; j++) gp[j] = 0.f;

#pragma unroll
    for (int i = 0; i < 8; i++) {
#pragma unroll
        for (int k = 0; k < 8; k++) {
            const int mi = MASKv[i];
            const int mk = MASKv[k];
            const int j = IDXv[mi ^ mk];
            const int s1 = ((mi >> 1) & mk);
            const int s2 = ((mi >> 2) & mk);
            const int sgn = ((s1 & 1) + ((s1 >> 1) & 1) + ((s1 >> 2) & 1)
                           + (s2 & 1) + ((s2 >> 1) & 1) + ((s2 >> 2) & 1)) & 1;
            const int p = PIDXv[GRDv[i]][GRDv[j]][GRDv[k]];
            float term = xv[i] * xrn[k];
            float ww = wp[p];
            gp[j] += sgn ? (-ww * term) : (ww * term);
        }
    }

    lf[0] += b_left[n];

    const float rs2 = 0.70710678118654752440f;
    float4 o0 = make_float4((lf[0] + gp[0]) * rs2, (lf[1] + gp[1]) * rs2,
                            (lf[2] + gp[2]) * rs2, (lf[3] + gp[3]) * rs2);
    float4 o1 = make_float4((lf[4] + gp[4]) * rs2, (lf[5] + gp[5]) * rs2,
                            (lf[6] + gp[6]) * rs2, (lf[7] + gp[7]) * rs2);
    *(float4*)&out[(size_t)t * 8] = o0;
    *(float4*)&out[(size_t)t * 8 + 4] = o1;
}

// ----------------------------------------------------------------------------
// Launch — inputs (metadata order): x, w_left, b_left, w_right, a_norm, w_gp
// ----------------------------------------------------------------------------
extern "C" void kernel_launch(void* const* d_in, const int* in_sizes, int n_in,
                              void* d_out, int out_size)
{
    const float* x       = (const float*)d_in[0];
    const float* w_left  = (const float*)d_in[1];
    const float* b_left  = (const float*)d_in[2];
    const float* w_right = (const float*)d_in[3];
    const float* a_norm  = (const float*)d_in[4];
    const float* w_gp    = (const float*)d_in[5];
    float* out = (float*)d_out;

    __half *xt, *wlt, *wrt;
    float *lp, *rp;
    cudaGetSymbolAddress((void**)&xt,  g_xt);
    cudaGetSymbolAddress((void**)&lp,  g_lp);
    cudaGetSymbolAddress((void**)&rp,  g_rp);
    cudaGetSymbolAddress((void**)&wlt, g_wl);
    cudaGetSymbolAddress((void**)&wrt, g_wr);

    k_transpose_x<<<BF / 256, 256>>>(x, xt);
    k_prep_w<<<(FDIM * FDIM) / 256, 256>>>(w_left, w_right, wlt, wrt);

    dim3 gg(BATCH / TM, FDIM / TN, NBL);
    k_gemm_mma<<<gg, 256>>>(xt, wlt, wrt, lp, rp);

    k_pointwise<<<BF / 256, 256>>>(x, lp, rp, b_left, a_norm, w_gp, out);
}